// round 1
// baseline (speedup 1.0000x reference)
#include <cuda_runtime.h>

#define N_   2
#define C_   256
#define H_   200
#define W_   304
#define HW_  (H_ * W_)
#define PH_  7
#define PW_  7
#define NBIN 49
#define NS   196          // 49 bins * 4 samples
#define SCALE 0.25f

// NHWC scratch (124.5 MB). __device__ global array is the sanctioned scratch mechanism.
__device__ float g_nhwc[(size_t)N_ * HW_ * C_];

// ---------------------------------------------------------------------------
// Kernel 1: NCHW -> NHWC transpose (per batch: C x HW  ->  HW x C)
// HW_ = 60800 = 1900*32, C_ = 256 = 8*32  -> no bounds checks needed.
// ---------------------------------------------------------------------------
__global__ void __launch_bounds__(256) nchw_to_nhwc(const float* __restrict__ in) {
    __shared__ float tile[32][33];
    const int n   = blockIdx.z;
    const int hw0 = blockIdx.x * 32;
    const int c0  = blockIdx.y * 32;
    const int tx  = threadIdx.x;
    const int ty  = threadIdx.y;

    const float* src = in + (size_t)n * C_ * HW_;
#pragma unroll
    for (int k = 0; k < 4; ++k)
        tile[ty + 8 * k][tx] = src[(size_t)(c0 + ty + 8 * k) * HW_ + hw0 + tx];

    __syncthreads();

    float* dst = g_nhwc + (size_t)n * HW_ * C_;
#pragma unroll
    for (int k = 0; k < 4; ++k)
        dst[(size_t)(hw0 + ty + 8 * k) * C_ + c0 + tx] = tile[tx][ty + 8 * k];
}

// ---------------------------------------------------------------------------
// Kernel 2: one block per ROI. 256 threads = 64 float4 channel-groups x 4 bin
// phases. Sample coords/weights precomputed into smem (196 samples).
// Output staged through a padded smem tile for a coalesced (C,49) store.
// ---------------------------------------------------------------------------
__global__ void __launch_bounds__(256) roi_align_rotated(
    const float* __restrict__ rois, float* __restrict__ out, int R) {
    extern __shared__ char smem_raw[];
    int*   s_off = (int*)smem_raw;                    // NS*4 ints   (3136 B)
    float* s_w   = (float*)(smem_raw + NS * 16);      // NS*4 floats (3136 B)
    float* s_out = (float*)(smem_raw + NS * 32);      // 49*257 floats (50372 B)

    const int r   = blockIdx.x;
    const int tid = threadIdx.x;

    if (tid < NS) {
        const float* rp = rois + (size_t)r * 6;
        const int   b     = (int)rp[0];
        const float cxr   = fmaf(rp[1], SCALE, -0.5f);
        const float cyr   = fmaf(rp[2], SCALE, -0.5f);
        const float rw    = rp[3] * SCALE;
        const float rh    = rp[4] * SCALE;
        const float theta = rp[5] * 0.017453292519943295f;  // pi/180
        float st, ct;
        sincosf(theta, &st, &ct);

        const float bin_h = rh * (1.0f / PH_);
        const float bin_w = rw * (1.0f / PW_);

        // sample id t = (ph*7+pw)*4 + gy*2 + gx
        const int g  = tid & 3;
        const int s  = tid >> 2;
        const int gy = g >> 1;
        const int gx = g & 1;
        const int ph = s / 7;
        const int pw = s - ph * 7;

        const float yy = -0.5f * rh + (float)ph * bin_h + ((float)gy + 0.5f) * bin_h * 0.5f;
        const float xx = -0.5f * rw + (float)pw * bin_w + ((float)gx + 0.5f) * bin_w * 0.5f;

        const float y = yy * ct - xx * st + cyr;
        const float x = yy * st + xx * ct + cxr;

        const bool valid = (y >= -1.0f) && (y <= (float)H_) &&
                           (x >= -1.0f) && (x <= (float)W_);

        const float yc = fminf(fmaxf(y, 0.0f), (float)(H_ - 1));
        const float xc = fminf(fmaxf(x, 0.0f), (float)(W_ - 1));
        const int   yl = (int)floorf(yc);
        const int   xl = (int)floorf(xc);
        const int   yh = min(yl + 1, H_ - 1);
        const int   xh = min(xl + 1, W_ - 1);
        const float ly = yc - (float)yl;
        const float lx = xc - (float)xl;
        const float hy = 1.0f - ly;
        const float hx = 1.0f - lx;
        const float wsc = valid ? 0.25f : 0.0f;   // fold mean over G*G=4 samples

        const int base = b * HW_;
        // offsets stored in float4 units (C_=256 divisible by 4)
        s_off[tid * 4 + 0] = (base + yl * W_ + xl) * (C_ / 4);
        s_off[tid * 4 + 1] = (base + yl * W_ + xh) * (C_ / 4);
        s_off[tid * 4 + 2] = (base + yh * W_ + xl) * (C_ / 4);
        s_off[tid * 4 + 3] = (base + yh * W_ + xh) * (C_ / 4);
        s_w[tid * 4 + 0] = hy * hx * wsc;
        s_w[tid * 4 + 1] = hy * lx * wsc;
        s_w[tid * 4 + 2] = ly * hx * wsc;
        s_w[tid * 4 + 3] = ly * lx * wsc;
    }
    __syncthreads();

    const float4* in4 = (const float4*)g_nhwc;
    const int cg = tid & 63;   // float4 channel group -> channels 4*cg..4*cg+3
    const int q  = tid >> 6;   // bin phase 0..3

    for (int s = q; s < NBIN; s += 4) {
        float4 acc = make_float4(0.f, 0.f, 0.f, 0.f);
#pragma unroll
        for (int g = 0; g < 4; ++g) {
            const int   t   = (s << 2) + g;
            const int4  off = ((const int4*)s_off)[t];
            const float4 w  = ((const float4*)s_w)[t];
            const float4 v0 = in4[off.x + cg];
            const float4 v1 = in4[off.y + cg];
            const float4 v2 = in4[off.z + cg];
            const float4 v3 = in4[off.w + cg];
            acc.x += w.x * v0.x + w.y * v1.x + w.z * v2.x + w.w * v3.x;
            acc.y += w.x * v0.y + w.y * v1.y + w.z * v2.y + w.w * v3.y;
            acc.z += w.x * v0.z + w.y * v1.z + w.z * v2.z + w.w * v3.z;
            acc.w += w.x * v0.w + w.y * v1.w + w.z * v2.w + w.w * v3.w;
        }
        float* po = s_out + s * 257 + cg * 4;
        po[0] = acc.x; po[1] = acc.y; po[2] = acc.z; po[3] = acc.w;
    }
    __syncthreads();

    // out[r][c][ph][pw] = s_out[s][c]; 257 padding -> conflict-free reads
    float* outr = out + (size_t)r * (C_ * NBIN);
    for (int idx = tid; idx < C_ * NBIN; idx += 256) {
        const int c  = idx / NBIN;
        const int sb = idx - c * NBIN;
        outr[idx] = s_out[sb * 257 + c];
    }
}

// ---------------------------------------------------------------------------
extern "C" void kernel_launch(void* const* d_in, const int* in_sizes, int n_in,
                              void* d_out, int out_size) {
    (void)n_in; (void)out_size;
    const float* input = (const float*)d_in[0];
    const float* rois  = (const float*)d_in[1];
    int roi_elems = in_sizes[1];
    // robustness: identify rois by size (R*6 is tiny vs the image)
    if (in_sizes[0] < in_sizes[1]) {
        input = (const float*)d_in[1];
        rois  = (const float*)d_in[0];
        roi_elems = in_sizes[0];
    }
    const int R = roi_elems / 6;
    float* out = (float*)d_out;

    nchw_to_nhwc<<<dim3(HW_ / 32, C_ / 32, N_), dim3(32, 8)>>>(input);

    const int smem_bytes = NS * 32 + NBIN * 257 * 4;  // 56644 B
    cudaFuncSetAttribute(roi_align_rotated,
                         cudaFuncAttributeMaxDynamicSharedMemorySize, smem_bytes);
    roi_align_rotated<<<R, 256, smem_bytes>>>(rois, out, R);
}

// round 2
// speedup vs baseline: 1.0960x; 1.0960x over previous
#include <cuda_runtime.h>

#define N_   2
#define C_   256
#define H_   200
#define W_   304
#define HW_  (H_ * W_)
#define PH_  7
#define PW_  7
#define NBIN 49
#define NS   196          // 49 bins * 4 samples
#define SCALE 0.25f
#define CH_HALF 128       // channels per block
#define QUADS  (CH_HALF / 4)   // 32 float4 channel-groups per block

// NHWC scratch (124.5 MB). __device__ global array is the sanctioned scratch mechanism.
__device__ float g_nhwc[(size_t)N_ * HW_ * C_];

// ---------------------------------------------------------------------------
// Kernel 1: NCHW -> NHWC transpose (per batch: C x HW  ->  HW x C)
// HW_ = 60800 = 1900*32, C_ = 256 = 8*32  -> no bounds checks needed.
// Conflict-free smem, both gmem sides fully coalesced.
// ---------------------------------------------------------------------------
__global__ void __launch_bounds__(256) nchw_to_nhwc(const float* __restrict__ in) {
    __shared__ float tile[32][33];
    const int n   = blockIdx.z;
    const int hw0 = blockIdx.x * 32;
    const int c0  = blockIdx.y * 32;
    const int tx  = threadIdx.x;
    const int ty  = threadIdx.y;

    const float* src = in + (size_t)n * C_ * HW_;
#pragma unroll
    for (int k = 0; k < 4; ++k)
        tile[ty + 8 * k][tx] = src[(size_t)(c0 + ty + 8 * k) * HW_ + hw0 + tx];

    __syncthreads();

    float* dst = g_nhwc + (size_t)n * HW_ * C_;
#pragma unroll
    for (int k = 0; k < 4; ++k)
        dst[(size_t)(hw0 + ty + 8 * k) * C_ + c0 + tx] = tile[tx][ty + 8 * k];
}

// ---------------------------------------------------------------------------
// Kernel 2: TWO blocks per ROI (channel halves) for occupancy + wave balance.
// 256 threads = 32 float4 channel-groups x 8 bin phases.
// Sample coords/weights precomputed into smem (196 samples, half-offset folded).
// Output staged through a padded smem tile for a coalesced (128ch, 49bin) store.
// ---------------------------------------------------------------------------
__global__ void __launch_bounds__(256) roi_align_rotated(
    const float* __restrict__ rois, float* __restrict__ out) {
    extern __shared__ char smem_raw[];
    int*   s_off = (int*)smem_raw;                    // NS*4 ints   (3136 B)
    float* s_w   = (float*)(smem_raw + NS * 16);      // NS*4 floats (3136 B)
    float* s_out = (float*)(smem_raw + NS * 32);      // 49*129 floats (25284 B)

    const int r    = blockIdx.x >> 1;
    const int half = blockIdx.x & 1;
    const int tid  = threadIdx.x;

    if (tid < NS) {
        const float* rp = rois + (size_t)r * 6;
        const int   b     = (int)rp[0];
        const float cxr   = fmaf(rp[1], SCALE, -0.5f);
        const float cyr   = fmaf(rp[2], SCALE, -0.5f);
        const float rw    = rp[3] * SCALE;
        const float rh    = rp[4] * SCALE;
        const float theta = rp[5] * 0.017453292519943295f;  // pi/180
        float st, ct;
        sincosf(theta, &st, &ct);

        const float bin_h = rh * (1.0f / PH_);
        const float bin_w = rw * (1.0f / PW_);

        // sample id t = (ph*7+pw)*4 + gy*2 + gx
        const int g  = tid & 3;
        const int s  = tid >> 2;
        const int gy = g >> 1;
        const int gx = g & 1;
        const int ph = s / 7;
        const int pw = s - ph * 7;

        const float yy = -0.5f * rh + (float)ph * bin_h + ((float)gy + 0.5f) * bin_h * 0.5f;
        const float xx = -0.5f * rw + (float)pw * bin_w + ((float)gx + 0.5f) * bin_w * 0.5f;

        const float y = yy * ct - xx * st + cyr;
        const float x = yy * st + xx * ct + cxr;

        const bool valid = (y >= -1.0f) && (y <= (float)H_) &&
                           (x >= -1.0f) && (x <= (float)W_);

        const float yc = fminf(fmaxf(y, 0.0f), (float)(H_ - 1));
        const float xc = fminf(fmaxf(x, 0.0f), (float)(W_ - 1));
        const int   yl = (int)floorf(yc);
        const int   xl = (int)floorf(xc);
        const int   yh = min(yl + 1, H_ - 1);
        const int   xh = min(xl + 1, W_ - 1);
        const float ly = yc - (float)yl;
        const float lx = xc - (float)xl;
        const float hy = 1.0f - ly;
        const float hx = 1.0f - lx;
        const float wsc = valid ? 0.25f : 0.0f;   // fold mean over G*G=4 samples

        const int base = b * HW_;
        const int hofs = half * QUADS;            // channel-half offset in float4 units
        // offsets stored in float4 units (C_=256 divisible by 4)
        s_off[tid * 4 + 0] = (base + yl * W_ + xl) * (C_ / 4) + hofs;
        s_off[tid * 4 + 1] = (base + yl * W_ + xh) * (C_ / 4) + hofs;
        s_off[tid * 4 + 2] = (base + yh * W_ + xl) * (C_ / 4) + hofs;
        s_off[tid * 4 + 3] = (base + yh * W_ + xh) * (C_ / 4) + hofs;
        s_w[tid * 4 + 0] = hy * hx * wsc;
        s_w[tid * 4 + 1] = hy * lx * wsc;
        s_w[tid * 4 + 2] = ly * hx * wsc;
        s_w[tid * 4 + 3] = ly * lx * wsc;
    }
    __syncthreads();

    const float4* in4 = (const float4*)g_nhwc;
    const int cg = tid & (QUADS - 1);   // float4 channel group within this half
    const int q  = tid >> 5;            // bin phase 0..7

    for (int s = q; s < NBIN; s += 8) {
        float4 acc = make_float4(0.f, 0.f, 0.f, 0.f);
#pragma unroll
        for (int g = 0; g < 4; ++g) {
            const int    t   = (s << 2) + g;
            const int4   off = ((const int4*)s_off)[t];
            const float4 w   = ((const float4*)s_w)[t];
            const float4 v0 = in4[off.x + cg];
            const float4 v1 = in4[off.y + cg];
            const float4 v2 = in4[off.z + cg];
            const float4 v3 = in4[off.w + cg];
            acc.x += w.x * v0.x + w.y * v1.x + w.z * v2.x + w.w * v3.x;
            acc.y += w.x * v0.y + w.y * v1.y + w.z * v2.y + w.w * v3.y;
            acc.z += w.x * v0.z + w.y * v1.z + w.z * v2.z + w.w * v3.z;
            acc.w += w.x * v0.w + w.y * v1.w + w.z * v2.w + w.w * v3.w;
        }
        float* po = s_out + s * (CH_HALF + 1) + cg * 4;
        po[0] = acc.x; po[1] = acc.y; po[2] = acc.z; po[3] = acc.w;
    }
    __syncthreads();

    // out[r][half*128+c][ph][pw] = s_out[s][c]
    // stride 129 (mod 32 == 1) -> conflict-free smem reads; gmem fully coalesced
    float* outh = out + (size_t)r * (C_ * NBIN) + (size_t)half * (CH_HALF * NBIN);
    for (int idx = tid; idx < CH_HALF * NBIN; idx += 256) {
        const int c  = idx / NBIN;
        const int sb = idx - c * NBIN;
        outh[idx] = s_out[sb * (CH_HALF + 1) + c];
    }
}

// ---------------------------------------------------------------------------
extern "C" void kernel_launch(void* const* d_in, const int* in_sizes, int n_in,
                              void* d_out, int out_size) {
    (void)n_in; (void)out_size;
    const float* input = (const float*)d_in[0];
    const float* rois  = (const float*)d_in[1];
    int roi_elems = in_sizes[1];
    // robustness: identify rois by size (R*6 is tiny vs the image)
    if (in_sizes[0] < in_sizes[1]) {
        input = (const float*)d_in[1];
        rois  = (const float*)d_in[0];
        roi_elems = in_sizes[0];
    }
    const int R = roi_elems / 6;
    float* out = (float*)d_out;

    nchw_to_nhwc<<<dim3(HW_ / 32, C_ / 32, N_), dim3(32, 8)>>>(input);

    const int smem_bytes = NS * 32 + NBIN * (CH_HALF + 1) * 4;  // 31556 B
    cudaFuncSetAttribute(roi_align_rotated,
                         cudaFuncAttributeMaxDynamicSharedMemorySize, smem_bytes);
    roi_align_rotated<<<R * 2, 256, smem_bytes>>>(rois, out);
}

// round 3
// speedup vs baseline: 1.7424x; 1.5898x over previous
#include <cuda_runtime.h>
#include <cuda_fp16.h>

#define N_   2
#define C_   256
#define H_   200
#define W_   304
#define HW_  (H_ * W_)
#define PH_  7
#define PW_  7
#define NBIN 49
#define NS   196          // 49 bins * 4 samples
#define SCALE 0.25f
#define CH_HALF 128       // channels per block
#define QUADS  (CH_HALF / 4)   // 32 4-channel groups per block

// NHWC fp16 scratch (62.3 MB) -> fully L2-resident on GB300 (126 MB L2).
__device__ __half g_nhwc[(size_t)N_ * HW_ * C_];

// ---------------------------------------------------------------------------
// Kernel 1: NCHW fp32 -> NHWC fp16 (per batch: C x HW -> HW x C), fused cvt.
// ---------------------------------------------------------------------------
__global__ void __launch_bounds__(256) nchw_to_nhwc(const float* __restrict__ in) {
    __shared__ float tile[32][33];
    const int n   = blockIdx.z;
    const int hw0 = blockIdx.x * 32;
    const int c0  = blockIdx.y * 32;
    const int tx  = threadIdx.x;
    const int ty  = threadIdx.y;

    const float* src = in + (size_t)n * C_ * HW_;
#pragma unroll
    for (int k = 0; k < 4; ++k)
        tile[ty + 8 * k][tx] = src[(size_t)(c0 + ty + 8 * k) * HW_ + hw0 + tx];

    __syncthreads();

    __half* dst = g_nhwc + (size_t)n * HW_ * C_;
#pragma unroll
    for (int k = 0; k < 4; ++k)
        dst[(size_t)(hw0 + ty + 8 * k) * C_ + c0 + tx] =
            __float2half_rn(tile[tx][ty + 8 * k]);
}

// ---------------------------------------------------------------------------
// fp16x4 fused accumulate: acc += w * cvt_f32(v)
// ---------------------------------------------------------------------------
__device__ __forceinline__ void acc4(float4& acc, float w, uint2 v) {
    const __half2 h0 = *reinterpret_cast<const __half2*>(&v.x);
    const __half2 h1 = *reinterpret_cast<const __half2*>(&v.y);
    const float2 f0 = __half22float2(h0);
    const float2 f1 = __half22float2(h1);
    acc.x = fmaf(w, f0.x, acc.x);
    acc.y = fmaf(w, f0.y, acc.y);
    acc.z = fmaf(w, f1.x, acc.z);
    acc.w = fmaf(w, f1.y, acc.w);
}

// ---------------------------------------------------------------------------
// Kernel 2: TWO blocks per ROI (channel halves). 256 threads = 32 channel
// groups x 8 bin phases. Coords/weights precomputed to smem; output staged
// through a padded smem tile for a coalesced (128ch, 49bin) fp32 store.
// ---------------------------------------------------------------------------
__global__ void __launch_bounds__(256) roi_align_rotated(
    const float* __restrict__ rois, float* __restrict__ out) {
    extern __shared__ char smem_raw[];
    int*   s_off = (int*)smem_raw;                    // NS*4 ints   (3136 B)
    float* s_w   = (float*)(smem_raw + NS * 16);      // NS*4 floats (3136 B)
    float* s_out = (float*)(smem_raw + NS * 32);      // 49*129 floats (25284 B)

    const int r    = blockIdx.x >> 1;
    const int half = blockIdx.x & 1;
    const int tid  = threadIdx.x;

    if (tid < NS) {
        const float* rp = rois + (size_t)r * 6;
        const int   b     = (int)rp[0];
        const float cxr   = fmaf(rp[1], SCALE, -0.5f);
        const float cyr   = fmaf(rp[2], SCALE, -0.5f);
        const float rw    = rp[3] * SCALE;
        const float rh    = rp[4] * SCALE;
        const float theta = rp[5] * 0.017453292519943295f;  // pi/180
        float st, ct;
        sincosf(theta, &st, &ct);

        const float bin_h = rh * (1.0f / PH_);
        const float bin_w = rw * (1.0f / PW_);

        // sample id t = (ph*7+pw)*4 + gy*2 + gx
        const int g  = tid & 3;
        const int s  = tid >> 2;
        const int gy = g >> 1;
        const int gx = g & 1;
        const int ph = s / 7;
        const int pw = s - ph * 7;

        const float yy = -0.5f * rh + (float)ph * bin_h + ((float)gy + 0.5f) * bin_h * 0.5f;
        const float xx = -0.5f * rw + (float)pw * bin_w + ((float)gx + 0.5f) * bin_w * 0.5f;

        const float y = yy * ct - xx * st + cyr;
        const float x = yy * st + xx * ct + cxr;

        const bool valid = (y >= -1.0f) && (y <= (float)H_) &&
                           (x >= -1.0f) && (x <= (float)W_);

        const float yc = fminf(fmaxf(y, 0.0f), (float)(H_ - 1));
        const float xc = fminf(fmaxf(x, 0.0f), (float)(W_ - 1));
        const int   yl = (int)floorf(yc);
        const int   xl = (int)floorf(xc);
        const int   yh = min(yl + 1, H_ - 1);
        const int   xh = min(xl + 1, W_ - 1);
        const float ly = yc - (float)yl;
        const float lx = xc - (float)xl;
        const float hy = 1.0f - ly;
        const float hx = 1.0f - lx;
        const float wsc = valid ? 0.25f : 0.0f;   // fold mean over G*G=4 samples

        const int base = b * HW_;
        const int hofs = half * QUADS;     // channel-half offset, uint2 (4-ch) units
        // offsets in uint2 units: C_/4 = 64 groups per pixel
        s_off[tid * 4 + 0] = (base + yl * W_ + xl) * (C_ / 4) + hofs;
        s_off[tid * 4 + 1] = (base + yl * W_ + xh) * (C_ / 4) + hofs;
        s_off[tid * 4 + 2] = (base + yh * W_ + xl) * (C_ / 4) + hofs;
        s_off[tid * 4 + 3] = (base + yh * W_ + xh) * (C_ / 4) + hofs;
        s_w[tid * 4 + 0] = hy * hx * wsc;
        s_w[tid * 4 + 1] = hy * lx * wsc;
        s_w[tid * 4 + 2] = ly * hx * wsc;
        s_w[tid * 4 + 3] = ly * lx * wsc;
    }
    __syncthreads();

    const uint2* in2 = (const uint2*)g_nhwc;
    const int cg = tid & (QUADS - 1);   // 4-channel group within this half
    const int q  = tid >> 5;            // bin phase 0..7

    for (int s = q; s < NBIN; s += 8) {
        float4 acc = make_float4(0.f, 0.f, 0.f, 0.f);
#pragma unroll
        for (int g = 0; g < 4; ++g) {
            const int    t   = (s << 2) + g;
            const int4   off = ((const int4*)s_off)[t];
            const float4 w   = ((const float4*)s_w)[t];
            const uint2 v0 = in2[off.x + cg];
            const uint2 v1 = in2[off.y + cg];
            const uint2 v2 = in2[off.z + cg];
            const uint2 v3 = in2[off.w + cg];
            acc4(acc, w.x, v0);
            acc4(acc, w.y, v1);
            acc4(acc, w.z, v2);
            acc4(acc, w.w, v3);
        }
        float* po = s_out + s * (CH_HALF + 1) + cg * 4;
        po[0] = acc.x; po[1] = acc.y; po[2] = acc.z; po[3] = acc.w;
    }
    __syncthreads();

    // out[r][half*128+c][ph][pw] = s_out[s][c]
    // stride 129 (mod 32 == 1) -> conflict-free smem reads; gmem fully coalesced
    float* outh = out + (size_t)r * (C_ * NBIN) + (size_t)half * (CH_HALF * NBIN);
    for (int idx = tid; idx < CH_HALF * NBIN; idx += 256) {
        const int c  = idx / NBIN;
        const int sb = idx - c * NBIN;
        outh[idx] = s_out[sb * (CH_HALF + 1) + c];
    }
}

// ---------------------------------------------------------------------------
extern "C" void kernel_launch(void* const* d_in, const int* in_sizes, int n_in,
                              void* d_out, int out_size) {
    (void)n_in; (void)out_size;
    const float* input = (const float*)d_in[0];
    const float* rois  = (const float*)d_in[1];
    int roi_elems = in_sizes[1];
    // robustness: identify rois by size (R*6 is tiny vs the image)
    if (in_sizes[0] < in_sizes[1]) {
        input = (const float*)d_in[1];
        rois  = (const float*)d_in[0];
        roi_elems = in_sizes[0];
    }
    const int R = roi_elems / 6;
    float* out = (float*)d_out;

    nchw_to_nhwc<<<dim3(HW_ / 32, C_ / 32, N_), dim3(32, 8)>>>(input);

    const int smem_bytes = NS * 32 + NBIN * (CH_HALF + 1) * 4;  // 31556 B
    cudaFuncSetAttribute(roi_align_rotated,
                         cudaFuncAttributeMaxDynamicSharedMemorySize, smem_bytes);
    roi_align_rotated<<<R * 2, 256, smem_bytes>>>(rois, out);
}

// round 4
// speedup vs baseline: 1.8799x; 1.0789x over previous
#include <cuda_runtime.h>
#include <cuda_fp16.h>

#define N_   2
#define C_   256
#define H_   200
#define W_   304
#define HW_  (H_ * W_)
#define PH_  7
#define PW_  7
#define NBIN 49
#define NS   196          // 49 bins * 4 samples
#define SCALE 0.25f
#define CH_HALF 128       // channels per gather block
#define QUADS  (CH_HALF / 4)   // 32 4-channel groups per block

typedef unsigned long long u64;

// NHWC fp16 scratch (62.3 MB) -> L2-resident on GB300 (126 MB L2).
__device__ __half g_nhwc[(size_t)N_ * HW_ * C_];

// ---------------------------------------------------------------------------
// Kernel 1: NCHW fp32 -> NHWC fp16. Tile = 128 channels x 32 hw positions.
// Loads: 128B/warp coalesced fp32, 16 outstanding per thread.
// Stores: half2-packed, 128B/warp contiguous.
// ---------------------------------------------------------------------------
__global__ void __launch_bounds__(256) nchw_to_nhwc(const float* __restrict__ in) {
    __shared__ float tile[128][33];
    const int n   = blockIdx.z;
    const int hw0 = blockIdx.x * 32;
    const int c0  = blockIdx.y * 128;
    const int t   = threadIdx.x;

    // load phase: warp = one channel row (32 contiguous hw floats)
    const int lrow = t >> 5;          // 0..7
    const int lcol = t & 31;
    const float* src = in + (size_t)n * C_ * HW_ + (size_t)c0 * HW_ + hw0;
#pragma unroll
    for (int p = 0; p < 16; ++p)
        tile[p * 8 + lrow][lcol] = src[(size_t)(p * 8 + lrow) * HW_ + lcol];

    __syncthreads();

    // store phase: 64 threads cover one hw row (128 ch as 64 half2)
    const int c2  = t & 63;           // half2 index within channel tile
    const int shw = t >> 6;           // 0..3
    __half* dst = g_nhwc + (size_t)n * HW_ * C_ + (size_t)hw0 * C_ + c0;
#pragma unroll
    for (int p = 0; p < 8; ++p) {
        const int hwr = p * 4 + shw;
        const float lo = tile[2 * c2 + 0][hwr];
        const float hi = tile[2 * c2 + 1][hwr];
        *reinterpret_cast<__half2*>(dst + (size_t)hwr * C_ + 2 * c2) =
            __floats2half2_rn(lo, hi);
    }
}

// ---------------------------------------------------------------------------
// packed f32x2 helpers
// ---------------------------------------------------------------------------
__device__ __forceinline__ u64 pack_ff(float lo, float hi) {
    u64 r;
    asm("mov.b64 %0, {%1, %2};" : "=l"(r) : "f"(lo), "f"(hi));
    return r;
}
__device__ __forceinline__ void unpack_ff(u64 v, float& lo, float& hi) {
    asm("mov.b64 {%0, %1}, %2;" : "=f"(lo), "=f"(hi) : "l"(v));
}
__device__ __forceinline__ u64 h2_to_f2(unsigned int h2) {
    const float2 f = __half22float2(*reinterpret_cast<const __half2*>(&h2));
    return pack_ff(f.x, f.y);
}
__device__ __forceinline__ void ffma2(u64& acc, u64 v, u64 w) {
    asm("fma.rn.f32x2 %0, %1, %2, %0;" : "+l"(acc) : "l"(v), "l"(w));
}

// ---------------------------------------------------------------------------
// Kernel 2: TWO blocks per ROI (channel halves). 256 threads = 32 channel
// groups x 8 bin phases. Coords/weights precomputed to smem; inner loop uses
// packed fma.rn.f32x2; output staged via padded smem for a coalesced store.
// ---------------------------------------------------------------------------
__global__ void __launch_bounds__(256) roi_align_rotated(
    const float* __restrict__ rois, float* __restrict__ out) {
    extern __shared__ char smem_raw[];
    int*   s_off = (int*)smem_raw;                    // NS*4 ints   (3136 B)
    float* s_w   = (float*)(smem_raw + NS * 16);      // NS*4 floats (3136 B)
    float* s_out = (float*)(smem_raw + NS * 32);      // 49*129 floats (25284 B)

    const int r    = blockIdx.x >> 1;
    const int half = blockIdx.x & 1;
    const int tid  = threadIdx.x;

    if (tid < NS) {
        const float* rp = rois + (size_t)r * 6;
        const int   b     = (int)rp[0];
        const float cxr   = fmaf(rp[1], SCALE, -0.5f);
        const float cyr   = fmaf(rp[2], SCALE, -0.5f);
        const float rw    = rp[3] * SCALE;
        const float rh    = rp[4] * SCALE;
        const float theta = rp[5] * 0.017453292519943295f;  // pi/180
        float st, ct;
        sincosf(theta, &st, &ct);

        const float bin_h = rh * (1.0f / PH_);
        const float bin_w = rw * (1.0f / PW_);

        // sample id t = (ph*7+pw)*4 + gy*2 + gx
        const int g  = tid & 3;
        const int s  = tid >> 2;
        const int gy = g >> 1;
        const int gx = g & 1;
        const int ph = s / 7;
        const int pw = s - ph * 7;

        const float yy = -0.5f * rh + (float)ph * bin_h + ((float)gy + 0.5f) * bin_h * 0.5f;
        const float xx = -0.5f * rw + (float)pw * bin_w + ((float)gx + 0.5f) * bin_w * 0.5f;

        const float y = yy * ct - xx * st + cyr;
        const float x = yy * st + xx * ct + cxr;

        const bool valid = (y >= -1.0f) && (y <= (float)H_) &&
                           (x >= -1.0f) && (x <= (float)W_);

        const float yc = fminf(fmaxf(y, 0.0f), (float)(H_ - 1));
        const float xc = fminf(fmaxf(x, 0.0f), (float)(W_ - 1));
        const int   yl = (int)floorf(yc);
        const int   xl = (int)floorf(xc);
        const int   yh = min(yl + 1, H_ - 1);
        const int   xh = min(xl + 1, W_ - 1);
        const float ly = yc - (float)yl;
        const float lx = xc - (float)xl;
        const float hy = 1.0f - ly;
        const float hx = 1.0f - lx;
        const float wsc = valid ? 0.25f : 0.0f;   // fold mean over G*G=4 samples

        const int base = b * HW_;
        const int hofs = half * QUADS;     // channel-half offset, uint2 (4-ch) units
        // offsets in uint2 units: C_/4 = 64 groups per pixel
        s_off[tid * 4 + 0] = (base + yl * W_ + xl) * (C_ / 4) + hofs;
        s_off[tid * 4 + 1] = (base + yl * W_ + xh) * (C_ / 4) + hofs;
        s_off[tid * 4 + 2] = (base + yh * W_ + xl) * (C_ / 4) + hofs;
        s_off[tid * 4 + 3] = (base + yh * W_ + xh) * (C_ / 4) + hofs;
        s_w[tid * 4 + 0] = hy * hx * wsc;
        s_w[tid * 4 + 1] = hy * lx * wsc;
        s_w[tid * 4 + 2] = ly * hx * wsc;
        s_w[tid * 4 + 3] = ly * lx * wsc;
    }
    __syncthreads();

    const uint2* __restrict__ in2 = (const uint2*)g_nhwc;
    const int cg = tid & (QUADS - 1);   // 4-channel group within this half
    const int q  = tid >> 5;            // bin phase 0..7

    for (int s = q; s < NBIN; s += 8) {
        u64 acc01 = 0ULL, acc23 = 0ULL;   // packed f32x2 accumulators (ch 0,1 | 2,3)
#pragma unroll
        for (int g = 0; g < 4; ++g) {
            const int    t   = (s << 2) + g;
            const int4   off = ((const int4*)s_off)[t];
            const float4 w   = ((const float4*)s_w)[t];
            const uint2 v0 = in2[off.x + cg];
            const uint2 v1 = in2[off.y + cg];
            const uint2 v2 = in2[off.z + cg];
            const uint2 v3 = in2[off.w + cg];
            const u64 w0 = pack_ff(w.x, w.x);
            const u64 w1 = pack_ff(w.y, w.y);
            const u64 w2 = pack_ff(w.z, w.z);
            const u64 w3 = pack_ff(w.w, w.w);
            ffma2(acc01, h2_to_f2(v0.x), w0);
            ffma2(acc23, h2_to_f2(v0.y), w0);
            ffma2(acc01, h2_to_f2(v1.x), w1);
            ffma2(acc23, h2_to_f2(v1.y), w1);
            ffma2(acc01, h2_to_f2(v2.x), w2);
            ffma2(acc23, h2_to_f2(v2.y), w2);
            ffma2(acc01, h2_to_f2(v3.x), w3);
            ffma2(acc23, h2_to_f2(v3.y), w3);
        }
        float* po = s_out + s * (CH_HALF + 1) + cg * 4;
        unpack_ff(acc01, po[0], po[1]);
        unpack_ff(acc23, po[2], po[3]);
    }
    __syncthreads();

    // out[r][half*128+c][ph][pw] = s_out[s][c]
    // stride 129 (mod 32 == 1) -> conflict-free smem reads; gmem fully coalesced
    float* outh = out + (size_t)r * (C_ * NBIN) + (size_t)half * (CH_HALF * NBIN);
    for (int idx = tid; idx < CH_HALF * NBIN; idx += 256) {
        const int c  = idx / NBIN;
        const int sb = idx - c * NBIN;
        outh[idx] = s_out[sb * (CH_HALF + 1) + c];
    }
}

// ---------------------------------------------------------------------------
extern "C" void kernel_launch(void* const* d_in, const int* in_sizes, int n_in,
                              void* d_out, int out_size) {
    (void)n_in; (void)out_size;
    const float* input = (const float*)d_in[0];
    const float* rois  = (const float*)d_in[1];
    int roi_elems = in_sizes[1];
    // robustness: identify rois by size (R*6 is tiny vs the image)
    if (in_sizes[0] < in_sizes[1]) {
        input = (const float*)d_in[1];
        rois  = (const float*)d_in[0];
        roi_elems = in_sizes[0];
    }
    const int R = roi_elems / 6;
    float* out = (float*)d_out;

    nchw_to_nhwc<<<dim3(HW_ / 32, C_ / 128, N_), 256>>>(input);

    const int smem_bytes = NS * 32 + NBIN * (CH_HALF + 1) * 4;  // 31556 B
    cudaFuncSetAttribute(roi_align_rotated,
                         cudaFuncAttributeMaxDynamicSharedMemorySize, smem_bytes);
    roi_align_rotated<<<R * 2, 256, smem_bytes>>>(rois, out);
}

// round 5
// speedup vs baseline: 2.0909x; 1.1123x over previous
#include <cuda_runtime.h>
#include <cuda_fp16.h>

#define N_   2
#define C_   256
#define H_   200
#define W_   304
#define HW_  (H_ * W_)
#define PH_  7
#define PW_  7
#define NBIN 49
#define NS   196          // 49 bins * 4 samples
#define SCALE 0.25f
#define CH_Q   64               // channels per gather block (quarter)
#define GRP    (CH_Q / 4)       // 16 4-channel (uint2) groups per block

// NHWC fp16 scratch (62.3 MB) -> L2-resident on GB300 (126 MB L2).
__device__ __half g_nhwc[(size_t)N_ * HW_ * C_];

// ---------------------------------------------------------------------------
// Kernel 1: NCHW fp32 -> NHWC fp16. Tile = 128 channels x 32 hw positions.
// Reads use evict-first (__ldcs) so they don't flush the NHWC image from L2.
// ---------------------------------------------------------------------------
__global__ void __launch_bounds__(256) nchw_to_nhwc(const float* __restrict__ in) {
    __shared__ float tile[128][33];
    const int n   = blockIdx.z;
    const int hw0 = blockIdx.x * 32;
    const int c0  = blockIdx.y * 128;
    const int t   = threadIdx.x;

    // load phase: warp = one channel row (32 contiguous hw floats)
    const int lrow = t >> 5;          // 0..7
    const int lcol = t & 31;
    const float* src = in + (size_t)n * C_ * HW_ + (size_t)c0 * HW_ + hw0;
#pragma unroll
    for (int p = 0; p < 16; ++p)
        tile[p * 8 + lrow][lcol] = __ldcs(&src[(size_t)(p * 8 + lrow) * HW_ + lcol]);

    __syncthreads();

    // store phase: 64 threads cover one hw row (128 ch as 64 half2)
    const int c2  = t & 63;           // half2 index within channel tile
    const int shw = t >> 6;           // 0..3
    __half* dst = g_nhwc + (size_t)n * HW_ * C_ + (size_t)hw0 * C_ + c0;
#pragma unroll
    for (int p = 0; p < 8; ++p) {
        const int hwr = p * 4 + shw;
        const float lo = tile[2 * c2 + 0][hwr];
        const float hi = tile[2 * c2 + 1][hwr];
        *reinterpret_cast<__half2*>(dst + (size_t)hwr * C_ + 2 * c2) =
            __floats2half2_rn(lo, hi);
    }
}

__device__ __forceinline__ __half2 as_h2(unsigned int v) {
    return *reinterpret_cast<const __half2*>(&v);
}

// ---------------------------------------------------------------------------
// Kernel 2: FOUR blocks per ROI (64-channel quarters) -> 19.0 KB smem,
// 8 blocks/SM. 256 threads = 16 channel groups x 16 bin phases.
// Bilinear interp per sample in HFMA2 (weights pre-packed as half2),
// cross-sample mean accumulated in fp32. Output staged via padded smem.
// ---------------------------------------------------------------------------
__global__ void __launch_bounds__(256, 8) roi_align_rotated(
    const float* __restrict__ rois, float* __restrict__ out) {
    extern __shared__ char smem_raw[];
    int*          s_off = (int*)smem_raw;                    // NS*4 ints    (3136 B)
    unsigned int* s_wh  = (unsigned int*)(smem_raw + NS*16); // NS*4 half2   (3136 B)
    float*        s_out = (float*)(smem_raw + NS * 32);      // 49*65 floats (12740 B)

    const int r    = blockIdx.x >> 2;
    const int quad = blockIdx.x & 3;
    const int tid  = threadIdx.x;

    if (tid < NS) {
        const float* rp = rois + (size_t)r * 6;
        const int   b     = (int)rp[0];
        const float cxr   = fmaf(rp[1], SCALE, -0.5f);
        const float cyr   = fmaf(rp[2], SCALE, -0.5f);
        const float rw    = rp[3] * SCALE;
        const float rh    = rp[4] * SCALE;
        const float theta = rp[5] * 0.017453292519943295f;  // pi/180
        float st, ct;
        sincosf(theta, &st, &ct);

        const float bin_h = rh * (1.0f / PH_);
        const float bin_w = rw * (1.0f / PW_);

        // sample id t = (ph*7+pw)*4 + gy*2 + gx
        const int g  = tid & 3;
        const int s  = tid >> 2;
        const int gy = g >> 1;
        const int gx = g & 1;
        const int ph = s / 7;
        const int pw = s - ph * 7;

        const float yy = -0.5f * rh + (float)ph * bin_h + ((float)gy + 0.5f) * bin_h * 0.5f;
        const float xx = -0.5f * rw + (float)pw * bin_w + ((float)gx + 0.5f) * bin_w * 0.5f;

        const float y = yy * ct - xx * st + cyr;
        const float x = yy * st + xx * ct + cxr;

        const bool valid = (y >= -1.0f) && (y <= (float)H_) &&
                           (x >= -1.0f) && (x <= (float)W_);

        const float yc = fminf(fmaxf(y, 0.0f), (float)(H_ - 1));
        const float xc = fminf(fmaxf(x, 0.0f), (float)(W_ - 1));
        const int   yl = (int)floorf(yc);
        const int   xl = (int)floorf(xc);
        const int   yh = min(yl + 1, H_ - 1);
        const int   xh = min(xl + 1, W_ - 1);
        const float ly = yc - (float)yl;
        const float lx = xc - (float)xl;
        const float hy = 1.0f - ly;
        const float hx = 1.0f - lx;
        const float vf = valid ? 1.0f : 0.0f;    // 0.25 mean factor applied in fp32

        const int base = b * HW_;
        const int hofs = quad * GRP;       // channel-quarter offset, uint2 (4-ch) units
        s_off[tid * 4 + 0] = (base + yl * W_ + xl) * (C_ / 4) + hofs;
        s_off[tid * 4 + 1] = (base + yl * W_ + xh) * (C_ / 4) + hofs;
        s_off[tid * 4 + 2] = (base + yh * W_ + xl) * (C_ / 4) + hofs;
        s_off[tid * 4 + 3] = (base + yh * W_ + xh) * (C_ / 4) + hofs;
        const __half2 w0 = __float2half2_rn(hy * hx * vf);
        const __half2 w1 = __float2half2_rn(hy * lx * vf);
        const __half2 w2 = __float2half2_rn(ly * hx * vf);
        const __half2 w3 = __float2half2_rn(ly * lx * vf);
        s_wh[tid * 4 + 0] = *reinterpret_cast<const unsigned int*>(&w0);
        s_wh[tid * 4 + 1] = *reinterpret_cast<const unsigned int*>(&w1);
        s_wh[tid * 4 + 2] = *reinterpret_cast<const unsigned int*>(&w2);
        s_wh[tid * 4 + 3] = *reinterpret_cast<const unsigned int*>(&w3);
    }
    __syncthreads();

    const uint2* __restrict__ in2 = (const uint2*)g_nhwc;
    const int cg = tid & (GRP - 1);   // 4-channel group within this quarter
    const int q  = tid >> 4;          // bin phase 0..15

    for (int s = q; s < NBIN; s += 16) {
        float4 acc = make_float4(0.f, 0.f, 0.f, 0.f);
#pragma unroll
        for (int g = 0; g < 4; ++g) {
            const int   t   = (s << 2) + g;
            const int4  off = ((const int4*)s_off)[t];
            const uint4 wp  = ((const uint4*)s_wh)[t];
            const uint2 v0 = in2[off.x + cg];
            const uint2 v1 = in2[off.y + cg];
            const uint2 v2 = in2[off.z + cg];
            const uint2 v3 = in2[off.w + cg];
            // fp16 bilinear within the sample (weights are convex, <= 1)
            __half2 a0 = __hmul2(as_h2(v0.x), as_h2(wp.x));
            __half2 a1 = __hmul2(as_h2(v0.y), as_h2(wp.x));
            a0 = __hfma2(as_h2(v1.x), as_h2(wp.y), a0);
            a1 = __hfma2(as_h2(v1.y), as_h2(wp.y), a1);
            a0 = __hfma2(as_h2(v2.x), as_h2(wp.z), a0);
            a1 = __hfma2(as_h2(v2.y), as_h2(wp.z), a1);
            a0 = __hfma2(as_h2(v3.x), as_h2(wp.w), a0);
            a1 = __hfma2(as_h2(v3.y), as_h2(wp.w), a1);
            // fp32 mean accumulation across the 4 samples
            const float2 f0 = __half22float2(a0);
            const float2 f1 = __half22float2(a1);
            acc.x = fmaf(0.25f, f0.x, acc.x);
            acc.y = fmaf(0.25f, f0.y, acc.y);
            acc.z = fmaf(0.25f, f1.x, acc.z);
            acc.w = fmaf(0.25f, f1.y, acc.w);
        }
        float* po = s_out + s * (CH_Q + 1) + cg * 4;
        po[0] = acc.x; po[1] = acc.y; po[2] = acc.z; po[3] = acc.w;
    }
    __syncthreads();

    // out[r][quad*64+c][ph][pw] = s_out[s][c]
    // stride 65 (mod 32 == 1) -> conflict-free smem reads; gmem fully coalesced
    float* outq = out + (size_t)r * (C_ * NBIN) + (size_t)quad * (CH_Q * NBIN);
    for (int idx = tid; idx < CH_Q * NBIN; idx += 256) {
        const int c  = idx / NBIN;
        const int sb = idx - c * NBIN;
        outq[idx] = s_out[sb * (CH_Q + 1) + c];
    }
}

// ---------------------------------------------------------------------------
extern "C" void kernel_launch(void* const* d_in, const int* in_sizes, int n_in,
                              void* d_out, int out_size) {
    (void)n_in; (void)out_size;
    const float* input = (const float*)d_in[0];
    const float* rois  = (const float*)d_in[1];
    int roi_elems = in_sizes[1];
    // robustness: identify rois by size (R*6 is tiny vs the image)
    if (in_sizes[0] < in_sizes[1]) {
        input = (const float*)d_in[1];
        rois  = (const float*)d_in[0];
        roi_elems = in_sizes[0];
    }
    const int R = roi_elems / 6;
    float* out = (float*)d_out;

    nchw_to_nhwc<<<dim3(HW_ / 32, C_ / 128, N_), 256>>>(input);

    const int smem_bytes = NS * 32 + NBIN * (CH_Q + 1) * 4;  // 19012 B
    cudaFuncSetAttribute(roi_align_rotated,
                         cudaFuncAttributeMaxDynamicSharedMemorySize, smem_bytes);
    roi_align_rotated<<<R * 4, 256, smem_bytes>>>(rois, out);
}

// round 6
// speedup vs baseline: 2.1536x; 1.0300x over previous
#include <cuda_runtime.h>
#include <cuda_fp16.h>

#define N_   2
#define C_   256
#define H_   200
#define W_   304
#define HW_  (H_ * W_)
#define PH_  7
#define PW_  7
#define NBIN 49
#define NS   196          // 49 bins * 4 samples
#define SCALE 0.25f
#define CH_Q   64               // channels per gather block (quarter)
#define GRP    (CH_Q / 4)       // 16 4-channel (uint2) groups per block

// NHWC fp16 scratch (62.3 MB) -> L2-resident on GB300 (126 MB L2).
__device__ __half g_nhwc[(size_t)N_ * HW_ * C_];

// ---------------------------------------------------------------------------
// Kernel 1: NCHW fp32 -> NHWC fp16. Tile = 128 channels x 32 hw positions.
// half2 conversion at load phase; smem tile is uint[32][65] (conflict-free
// STS). Store phase: one STG.128 per thread per pass (8 contiguous channels).
// ---------------------------------------------------------------------------
__global__ void __launch_bounds__(256) nchw_to_nhwc(const float* __restrict__ in) {
    __shared__ unsigned int tile[32 * 65];   // [hw][channel-pair], pad 65
    const int n   = blockIdx.z;
    const int hw0 = blockIdx.x * 32;
    const int c0  = blockIdx.y * 128;
    const int t   = threadIdx.x;
    const int w   = t >> 5;     // warp 0..7
    const int l   = t & 31;     // lane = hw offset

    const float* src = in + (size_t)n * C_ * HW_ + (size_t)c0 * HW_ + hw0;
#pragma unroll
    for (int i = 0; i < 8; ++i) {
        const int cp = i * 8 + w;                       // channel pair 0..63
        const float f0 = __ldcs(&src[(size_t)(2 * cp + 0) * HW_ + l]);
        const float f1 = __ldcs(&src[(size_t)(2 * cp + 1) * HW_ + l]);
        const __half2 h = __floats2half2_rn(f0, f1);
        tile[l * 65 + cp] = *reinterpret_cast<const unsigned int*>(&h);
    }
    __syncthreads();

    __half* dst = g_nhwc + (size_t)n * HW_ * C_ + (size_t)hw0 * C_ + c0;
    const int c16 = t & 15;     // 8-channel group (4 uints)
    const int sh  = t >> 4;     // 0..15
#pragma unroll
    for (int pass = 0; pass < 2; ++pass) {
        const int hwr = pass * 16 + sh;
        uint4 v;
        v.x = tile[hwr * 65 + 4 * c16 + 0];
        v.y = tile[hwr * 65 + 4 * c16 + 1];
        v.z = tile[hwr * 65 + 4 * c16 + 2];
        v.w = tile[hwr * 65 + 4 * c16 + 3];
        *reinterpret_cast<uint4*>(dst + (size_t)hwr * C_ + 8 * c16) = v;
    }
}

__device__ __forceinline__ __half2 as_h2(unsigned int v) {
    return *reinterpret_cast<const __half2*>(&v);
}

// ---------------------------------------------------------------------------
// Kernel 2: FOUR blocks per ROI (64-channel quarters), 8 blocks/SM.
// 256 threads = 16 channel groups x 16 bin phases. Each PAIR of samples is
// one fused fp16 chain (8 corner terms), converted to fp32 once per pair.
// ---------------------------------------------------------------------------
__global__ void __launch_bounds__(256, 8) roi_align_rotated(
    const float* __restrict__ rois, float* __restrict__ out) {
    extern __shared__ char smem_raw[];
    int*          s_off = (int*)smem_raw;                    // NS*4 ints    (3136 B)
    unsigned int* s_wh  = (unsigned int*)(smem_raw + NS*16); // NS*4 half2   (3136 B)
    float*        s_out = (float*)(smem_raw + NS * 32);      // 49*65 floats (12740 B)

    const int r    = blockIdx.x >> 2;
    const int quad = blockIdx.x & 3;
    const int tid  = threadIdx.x;

    if (tid < NS) {
        const float* rp = rois + (size_t)r * 6;
        const int   b     = (int)rp[0];
        const float cxr   = fmaf(rp[1], SCALE, -0.5f);
        const float cyr   = fmaf(rp[2], SCALE, -0.5f);
        const float rw    = rp[3] * SCALE;
        const float rh    = rp[4] * SCALE;
        const float theta = rp[5] * 0.017453292519943295f;  // pi/180
        float st, ct;
        sincosf(theta, &st, &ct);

        const float bin_h = rh * (1.0f / PH_);
        const float bin_w = rw * (1.0f / PW_);

        // sample id t = (ph*7+pw)*4 + gy*2 + gx
        const int g  = tid & 3;
        const int s  = tid >> 2;
        const int gy = g >> 1;
        const int gx = g & 1;
        const int ph = s / 7;
        const int pw = s - ph * 7;

        const float yy = -0.5f * rh + (float)ph * bin_h + ((float)gy + 0.5f) * bin_h * 0.5f;
        const float xx = -0.5f * rw + (float)pw * bin_w + ((float)gx + 0.5f) * bin_w * 0.5f;

        const float y = yy * ct - xx * st + cyr;
        const float x = yy * st + xx * ct + cxr;

        const bool valid = (y >= -1.0f) && (y <= (float)H_) &&
                           (x >= -1.0f) && (x <= (float)W_);

        const float yc = fminf(fmaxf(y, 0.0f), (float)(H_ - 1));
        const float xc = fminf(fmaxf(x, 0.0f), (float)(W_ - 1));
        const int   yl = (int)floorf(yc);
        const int   xl = (int)floorf(xc);
        const int   yh = min(yl + 1, H_ - 1);
        const int   xh = min(xl + 1, W_ - 1);
        const float ly = yc - (float)yl;
        const float lx = xc - (float)xl;
        const float hy = 1.0f - ly;
        const float hx = 1.0f - lx;
        const float vf = valid ? 1.0f : 0.0f;    // 0.25 mean factor applied in fp32

        const int base = b * HW_;
        const int hofs = quad * GRP;       // channel-quarter offset, uint2 (4-ch) units
        s_off[tid * 4 + 0] = (base + yl * W_ + xl) * (C_ / 4) + hofs;
        s_off[tid * 4 + 1] = (base + yl * W_ + xh) * (C_ / 4) + hofs;
        s_off[tid * 4 + 2] = (base + yh * W_ + xl) * (C_ / 4) + hofs;
        s_off[tid * 4 + 3] = (base + yh * W_ + xh) * (C_ / 4) + hofs;
        const __half2 w0 = __float2half2_rn(hy * hx * vf);
        const __half2 w1 = __float2half2_rn(hy * lx * vf);
        const __half2 w2 = __float2half2_rn(ly * hx * vf);
        const __half2 w3 = __float2half2_rn(ly * lx * vf);
        s_wh[tid * 4 + 0] = *reinterpret_cast<const unsigned int*>(&w0);
        s_wh[tid * 4 + 1] = *reinterpret_cast<const unsigned int*>(&w1);
        s_wh[tid * 4 + 2] = *reinterpret_cast<const unsigned int*>(&w2);
        s_wh[tid * 4 + 3] = *reinterpret_cast<const unsigned int*>(&w3);
    }
    __syncthreads();

    const uint2* __restrict__ in2 = (const uint2*)g_nhwc;
    const int cg = tid & (GRP - 1);   // 4-channel group within this quarter
    const int q  = tid >> 4;          // bin phase 0..15

    for (int s = q; s < NBIN; s += 16) {
        float4 acc = make_float4(0.f, 0.f, 0.f, 0.f);
#pragma unroll
        for (int p = 0; p < 2; ++p) {       // two sample-pairs per bin
            const int   t0   = (s << 2) + 2 * p;
            const int4  offA = ((const int4*)s_off)[t0];
            const int4  offB = ((const int4*)s_off)[t0 + 1];
            const uint4 wA   = ((const uint4*)s_wh)[t0];
            const uint4 wB   = ((const uint4*)s_wh)[t0 + 1];
            const uint2 a0 = in2[offA.x + cg];
            const uint2 a1 = in2[offA.y + cg];
            const uint2 a2 = in2[offA.z + cg];
            const uint2 a3 = in2[offA.w + cg];
            const uint2 b0 = in2[offB.x + cg];
            const uint2 b1 = in2[offB.y + cg];
            const uint2 b2 = in2[offB.z + cg];
            const uint2 b3 = in2[offB.w + cg];
            // fused fp16 chain over 8 corner terms (2 samples)
            __half2 h0 = __hmul2(as_h2(a0.x), as_h2(wA.x));
            __half2 h1 = __hmul2(as_h2(a0.y), as_h2(wA.x));
            h0 = __hfma2(as_h2(a1.x), as_h2(wA.y), h0);
            h1 = __hfma2(as_h2(a1.y), as_h2(wA.y), h1);
            h0 = __hfma2(as_h2(a2.x), as_h2(wA.z), h0);
            h1 = __hfma2(as_h2(a2.y), as_h2(wA.z), h1);
            h0 = __hfma2(as_h2(a3.x), as_h2(wA.w), h0);
            h1 = __hfma2(as_h2(a3.y), as_h2(wA.w), h1);
            h0 = __hfma2(as_h2(b0.x), as_h2(wB.x), h0);
            h1 = __hfma2(as_h2(b0.y), as_h2(wB.x), h1);
            h0 = __hfma2(as_h2(b1.x), as_h2(wB.y), h0);
            h1 = __hfma2(as_h2(b1.y), as_h2(wB.y), h1);
            h0 = __hfma2(as_h2(b2.x), as_h2(wB.z), h0);
            h1 = __hfma2(as_h2(b2.y), as_h2(wB.z), h1);
            h0 = __hfma2(as_h2(b3.x), as_h2(wB.w), h0);
            h1 = __hfma2(as_h2(b3.y), as_h2(wB.w), h1);
            // one fp32 conversion per pair; 0.25 mean factor
            const float2 f0 = __half22float2(h0);
            const float2 f1 = __half22float2(h1);
            acc.x = fmaf(0.25f, f0.x, acc.x);
            acc.y = fmaf(0.25f, f0.y, acc.y);
            acc.z = fmaf(0.25f, f1.x, acc.z);
            acc.w = fmaf(0.25f, f1.y, acc.w);
        }
        float* po = s_out + s * (CH_Q + 1) + cg * 4;
        po[0] = acc.x; po[1] = acc.y; po[2] = acc.z; po[3] = acc.w;
    }
    __syncthreads();

    // out[r][quad*64+c][ph][pw] = s_out[s][c]
    // stride 65 (mod 32 == 1) -> conflict-free smem reads; gmem fully coalesced
    float* outq = out + (size_t)r * (C_ * NBIN) + (size_t)quad * (CH_Q * NBIN);
    for (int idx = tid; idx < CH_Q * NBIN; idx += 256) {
        const int c  = idx / NBIN;
        const int sb = idx - c * NBIN;
        outq[idx] = s_out[sb * (CH_Q + 1) + c];
    }
}

// ---------------------------------------------------------------------------
extern "C" void kernel_launch(void* const* d_in, const int* in_sizes, int n_in,
                              void* d_out, int out_size) {
    (void)n_in; (void)out_size;
    const float* input = (const float*)d_in[0];
    const float* rois  = (const float*)d_in[1];
    int roi_elems = in_sizes[1];
    // robustness: identify rois by size (R*6 is tiny vs the image)
    if (in_sizes[0] < in_sizes[1]) {
        input = (const float*)d_in[1];
        rois  = (const float*)d_in[0];
        roi_elems = in_sizes[0];
    }
    const int R = roi_elems / 6;
    float* out = (float*)d_out;

    nchw_to_nhwc<<<dim3(HW_ / 32, C_ / 128, N_), 256>>>(input);

    const int smem_bytes = NS * 32 + NBIN * (CH_Q + 1) * 4;  // 19012 B
    cudaFuncSetAttribute(roi_align_rotated,
                         cudaFuncAttributeMaxDynamicSharedMemorySize, smem_bytes);
    roi_align_rotated<<<R * 4, 256, smem_bytes>>>(rois, out);
}